// round 3
// baseline (speedup 1.0000x reference)
#include <cuda_runtime.h>
#include <cstdint>
#include <cstddef>

#define NB 16
#define NS 2048
#define ND 1024
#define NM 256
#define NROWS (NB*NS)   // 32768

// ---------------- scratch (device globals: allocation-free) ----------------
__device__ float g_xm[(size_t)NROWS * NM];
__device__ float g_xf[(size_t)NROWS * NM];
__device__ float g_xu[(size_t)NROWS * NM];
__device__ float g_H [(size_t)NROWS * NM];

// ---------------- helpers ----------------
__device__ __forceinline__ uint32_t f2tf32(float x) {
    uint32_t r; asm("cvt.rna.tf32.f32 %0, %1;" : "=r"(r) : "f"(x)); return r;
}
__device__ __forceinline__ void mma_tf32(float c[4], const uint32_t a[4], const uint32_t b[2]) {
    asm volatile("mma.sync.aligned.m16n8k8.row.col.f32.tf32.tf32.f32 "
        "{%0,%1,%2,%3}, {%4,%5,%6,%7}, {%8,%9}, {%0,%1,%2,%3};"
        : "+f"(c[0]), "+f"(c[1]), "+f"(c[2]), "+f"(c[3])
        : "r"(a[0]), "r"(a[1]), "r"(a[2]), "r"(a[3]), "r"(b[0]), "r"(b[1]));
}
__device__ __forceinline__ uint32_t smem_u32(const void* p) {
    return (uint32_t)__cvta_generic_to_shared(p);
}

#define MBAR_INIT(addr, cnt) \
    asm volatile("mbarrier.init.shared.b64 [%0], %1;" :: "r"(addr), "r"(cnt) : "memory")

#define MBAR_ARRIVE_EXPECT_TX(addr, tx) \
    asm volatile("mbarrier.arrive.expect_tx.shared.b64 _, [%0], %1;" \
                 :: "r"(addr), "r"(tx) : "memory")

#define MBAR_WAIT(addr, par) do {                                           \
    uint32_t _m = (addr); uint32_t _p = (par); uint32_t _done;              \
    asm volatile(                                                           \
        "{\n\t.reg .pred p;\n\t"                                            \
        "mbarrier.try_wait.parity.acquire.cluster.shared::cta.b64 p, [%1], %2;\n\t" \
        "selp.b32 %0, 1, 0, p;\n\t}"                                        \
        : "=r"(_done) : "r"(_m), "r"(_p) : "memory");                       \
    if (!_done) {                                                           \
        asm volatile(                                                       \
            "{\n\t.reg .pred P1;\n\t"                                       \
            "WAIT_LOOP_%=:\n\t"                                             \
            "mbarrier.try_wait.parity.acquire.cluster.shared::cta.b64 P1, [%0], %1, 0x989680;\n\t" \
            "@P1 bra.uni WAIT_DONE_%=;\n\t"                                 \
            "bra.uni WAIT_LOOP_%=;\n\t"                                     \
            "WAIT_DONE_%=:\n\t}"                                            \
            :: "r"(_m), "r"(_p) : "memory");                                \
    }                                                                       \
} while (0)

#define CLUSTER_SYNC_() do {                                                \
    asm volatile("barrier.cluster.arrive.aligned;" ::: "memory");           \
    asm volatile("barrier.cluster.wait.aligned;"   ::: "memory");           \
} while (0)

// =====================================================================
// GEMM: C[row, n] = sum_k A[row, k] * W[n, k]   (tf32 tensor cores)
// BM=128, BN=128, BK=16, 256 threads, 8 warps (4x2), warp tile 32x64
// MODE 0: A = X (K=1024), W in {Wi, Wf[:, :1024], Wu[:, :1024]}, N=768
//         epilogue: +bias, silu for xm; -> g_xm / g_xf / g_xu
// MODE 1: A = [X | H] (K=1280), W = Wo (ld 1280), N=1024
//         epilogue: + bo[n] + X[row, n]; -> out
// =====================================================================
template<int MODE>
__global__ void __launch_bounds__(256) gemm_kernel(
    const float* __restrict__ X,
    const float* __restrict__ Wi, const float* __restrict__ bi,
    const float* __restrict__ Wf, const float* __restrict__ bf,
    const float* __restrict__ Wu, const float* __restrict__ bu,
    const float* __restrict__ Wo, const float* __restrict__ bo,
    float* __restrict__ out)
{
    __shared__ uint32_t As[2][128][20];
    __shared__ uint32_t Bs[2][128][20];

    const int tid  = threadIdx.x;
    const int lane = tid & 31;
    const int warp = tid >> 5;
    const int wm   = warp >> 1;   // 0..3
    const int wn   = warp & 1;    // 0..1
    const int bm   = blockIdx.x;
    const int bn   = blockIdx.y;
    const int row0 = bm * 128;
    const int col0 = bn * 128;

    const float* Bmat; int ldb; int K; int nbase;
    const float* bias = bi; float* dst = g_xm; int seg = 0;
    if (MODE == 0) {
        K = 1024;
        seg = bn >> 1;
        Bmat = (seg == 0) ? Wi : ((seg == 1) ? Wf : Wu);
        ldb  = (seg == 0) ? 1024 : 1280;
        nbase = (bn & 1) * 128;
        bias = (seg == 0) ? bi : ((seg == 1) ? bf : bu);
        dst  = (seg == 0) ? g_xm : ((seg == 1) ? g_xf : g_xu);
    } else {
        K = 1280; Bmat = Wo; ldb = 1280; nbase = col0;
    }
    const int NKT = K / 16;

    const int lr = tid >> 2;        // 0..63
    const int lc = (tid & 3) * 4;   // 0,4,8,12

    float acc[2][8][4];
    #pragma unroll
    for (int i = 0; i < 2; i++)
        #pragma unroll
        for (int j = 0; j < 8; j++)
            #pragma unroll
            for (int k = 0; k < 4; k++) acc[i][j][k] = 0.f;

    float4 ra[2], rb[2];

    // ---- global loaders ----
    auto ldgA = [&](int kt) {
        const int kk = kt * 16 + lc;
        #pragma unroll
        for (int h = 0; h < 2; ++h) {
            const int rr = row0 + lr + h * 64;
            if (MODE == 1 && kk >= 1024)
                ra[h] = *(const float4*)(g_H + (size_t)rr * NM + (kk - 1024));
            else
                ra[h] = *(const float4*)(X + (size_t)rr * ND + kk);
        }
    };
    auto ldgB = [&](int kt) {
        const int kk = kt * 16 + lc;
        #pragma unroll
        for (int h = 0; h < 2; ++h) {
            const int rr = nbase + lr + h * 64;
            rb[h] = *(const float4*)(Bmat + (size_t)rr * ldb + kk);
        }
    };
    auto stsAB = [&](int buf) {
        #pragma unroll
        for (int h = 0; h < 2; ++h) {
            uint32_t* pa = &As[buf][lr + h * 64][lc];
            pa[0] = f2tf32(ra[h].x); pa[1] = f2tf32(ra[h].y);
            pa[2] = f2tf32(ra[h].z); pa[3] = f2tf32(ra[h].w);
            uint32_t* pb = &Bs[buf][lr + h * 64][lc];
            pb[0] = f2tf32(rb[h].x); pb[1] = f2tf32(rb[h].y);
            pb[2] = f2tf32(rb[h].z); pb[3] = f2tf32(rb[h].w);
        }
    };
    auto compute = [&](int buf) {
        #pragma unroll
        for (int ks = 0; ks < 2; ++ks) {
            const int k0 = ks * 8 + (lane & 3);
            uint32_t a[2][4]; uint32_t bb[8][2];
            #pragma unroll
            for (int mf = 0; mf < 2; ++mf) {
                const int r = wm * 32 + mf * 16 + (lane >> 2);
                a[mf][0] = As[buf][r    ][k0];
                a[mf][1] = As[buf][r + 8][k0];
                a[mf][2] = As[buf][r    ][k0 + 4];
                a[mf][3] = As[buf][r + 8][k0 + 4];
            }
            #pragma unroll
            for (int nf = 0; nf < 8; ++nf) {
                const int c = wn * 64 + nf * 8 + (lane >> 2);
                bb[nf][0] = Bs[buf][c][k0];
                bb[nf][1] = Bs[buf][c][k0 + 4];
            }
            #pragma unroll
            for (int mf = 0; mf < 2; ++mf)
                #pragma unroll
                for (int nf = 0; nf < 8; ++nf)
                    mma_tf32(acc[mf][nf], a[mf], bb[nf]);
        }
    };

    // ---- main loop (double buffered) ----
    ldgA(0); ldgB(0);
    stsAB(0);
    __syncthreads();
    for (int kt = 0; kt < NKT; ++kt) {
        const int buf = kt & 1;
        if (kt + 1 < NKT) { ldgA(kt + 1); ldgB(kt + 1); }
        compute(buf);
        if (kt + 1 < NKT) stsAB(buf ^ 1);
        __syncthreads();
    }

    // ---- epilogue ----
    #pragma unroll
    for (int mf = 0; mf < 2; ++mf)
        #pragma unroll
        for (int nf = 0; nf < 8; ++nf)
            #pragma unroll
            for (int h = 0; h < 2; ++h) {
                const int row = row0 + wm * 32 + mf * 16 + (lane >> 2) + h * 8;
                const int c0  = col0 + wn * 64 + nf * 8 + (lane & 3) * 2;
                float v0 = acc[mf][nf][h * 2 + 0];
                float v1 = acc[mf][nf][h * 2 + 1];
                if (MODE == 0) {
                    const int cl = c0 & 255;
                    v0 += bias[cl]; v1 += bias[cl + 1];
                    if (seg == 0) {
                        v0 = v0 / (1.f + __expf(-v0));
                        v1 = v1 / (1.f + __expf(-v1));
                    }
                    *(float2*)&dst[(size_t)row * NM + cl] = make_float2(v0, v1);
                } else {
                    v0 += bo[c0]     + X[(size_t)row * ND + c0];
                    v1 += bo[c0 + 1] + X[(size_t)row * ND + c0 + 1];
                    *(float2*)&out[(size_t)row * ND + c0] = make_float2(v0, v1);
                }
            }
}

// =====================================================================
// Recurrence v2: 16 clusters x 8 CTAs (one cluster per batch), 256 thr.
// Warp w (0..7): gate g = w>>2 (0=f via WfH, 1=u via WuH).
// Lane l: jj = (w&3)*8 + (l>>2)  (local row 0..31),  kq = l&3 (k-quarter).
// k-reduction via shfl (intra-warp). One __syncthreads per step (u->f).
// h broadcast to all 8 CTAs via st.async.b64 + transaction mbarriers
// (double buffered) -- no cluster barrier in the loop.
// =====================================================================
__global__ void __cluster_dims__(8, 1, 1) __launch_bounds__(256)
recur_kernel(const float* __restrict__ Wf, const float* __restrict__ Wu,
             float* __restrict__ hfinal)
{
    const int tid  = threadIdx.x;
    const int lane = tid & 31;
    const int w    = tid >> 5;
    const int g    = w >> 2;                 // 0: f, 1: u
    const int jj   = (w & 3) * 8 + (lane >> 2);
    const int kq   = lane & 3;
    const int r    = blockIdx.x & 7;         // slice (cluster rank)
    const int b    = blockIdx.x >> 3;        // batch
    const int j    = r * 32 + jj;            // only meaningful per-warp-row
    const int k0   = kq * 64;

    __shared__ alignas(16) float h_sm[2][256];
    __shared__ float t2_s[32];
    __shared__ alignas(8) unsigned long long mbar[2];

    const uint32_t mb0 = smem_u32(&mbar[0]);
    const uint32_t mb1 = smem_u32(&mbar[1]);

    // ---- recurrent weights into registers (64 per thread) ----
    float wreg[64];
    {
        const float* Wsrc = g ? Wu : Wf;
        const float* p = Wsrc + (size_t)j * 1280 + 1024 + k0;
        #pragma unroll
        for (int i = 0; i < 16; ++i) {
            float4 v = *(const float4*)(p + i * 4);
            wreg[4*i+0] = v.x; wreg[4*i+1] = v.y;
            wreg[4*i+2] = v.z; wreg[4*i+3] = v.w;
        }
    }

    // ---- precompute remote addresses (senders: f-warps, (lane&4)==0) ----
    // sender lane owns row pair (jj, jj+1) and dest CTAs {2*kq, 2*kq+1}
    uint32_t rd0[2], rd1[2], rm0[2], rm1[2];
    {
        const uint32_t ld0 = smem_u32(&h_sm[0][j]);
        const uint32_t ld1 = smem_u32(&h_sm[1][j]);
        #pragma unroll
        for (int d2 = 0; d2 < 2; ++d2) {
            const int dst = kq * 2 + d2;
            asm("mapa.shared::cluster.u32 %0, %1, %2;" : "=r"(rd0[d2]) : "r"(ld0), "r"(dst));
            asm("mapa.shared::cluster.u32 %0, %1, %2;" : "=r"(rd1[d2]) : "r"(ld1), "r"(dst));
            asm("mapa.shared::cluster.u32 %0, %1, %2;" : "=r"(rm0[d2]) : "r"(mb0), "r"(dst));
            asm("mapa.shared::cluster.u32 %0, %1, %2;" : "=r"(rm1[d2]) : "r"(mb1), "r"(dst));
        }
    }

    // ---- input prefetch streams (2 deep) ----
    const size_t base = (size_t)b * NS * NM + j;
    const float* px0 = (g ? g_xu : g_xf) + base;  // stride NM per t
    const float* px1 = g_xm + base;               // u-warps only
    float x0a = px0[0], x0b = px0[NM];
    float x1a = 0.f, x1b = 0.f;
    if (g) { x1a = px1[0]; x1b = px1[NM]; }

    // ---- init ----
    h_sm[0][tid] = 0.f;
    if (tid == 0) { MBAR_INIT(mb0, 1); MBAR_INIT(mb1, 1); }
    __syncthreads();
    CLUSTER_SYNC_();   // mbarriers visible cluster-wide before any st.async

    int ph0 = 0, ph1 = 0;
    float h_reg = 0.f;   // f-warps: running h[j]

    for (int t = 0; t < NS; ++t) {
        const int buf = t & 1;

        // wait for this step's h buffer (arrives via st.async)
        if (t > 0) {
            if (buf) { MBAR_WAIT(mb1, ph1); ph1 ^= 1; }
            else     { MBAR_WAIT(mb0, ph0); ph0 ^= 1; }
        }
        // post expectation for next step's buffer: 8 CTAs x 32 floats = 1024B
        if (tid == 0 && t + 1 < NS) {
            MBAR_ARRIVE_EXPECT_TX(buf ? mb0 : mb1, 1024);
        }

        // ---- dot over k quarter: acc = sum wreg[k]*h[k0+k] ----
        float a0 = 0.f, a1 = 0.f, a2 = 0.f, a3 = 0.f;
        {
            const float4* hv = (const float4*)&h_sm[buf][k0];
            #pragma unroll
            for (int i = 0; i < 16; ++i) {
                const float4 v = hv[i];
                a0 = fmaf(wreg[4*i+0], v.x, a0);
                a1 = fmaf(wreg[4*i+1], v.y, a1);
                a2 = fmaf(wreg[4*i+2], v.z, a2);
                a3 = fmaf(wreg[4*i+3], v.w, a3);
            }
        }
        float acc = (a0 + a1) + (a2 + a3);
        acc += __shfl_xor_sync(0xffffffffu, acc, 1);
        acc += __shfl_xor_sync(0xffffffffu, acc, 2);   // full row dot (per kq dup)

        // ---- gate + input stream consume/refill ----
        const float xc = buf ? x0b : x0a;
        if (t + 2 < NS) {
            const float nv = px0[(size_t)(t + 2) * NM];
            if (buf) x0b = nv; else x0a = nv;
        }
        const float z  = acc + xc;
        const float sg = 1.f / (1.f + __expf(-z));

        if (g) {
            const float xmv = buf ? x1b : x1a;
            if (t + 2 < NS) {
                const float nv = px1[(size_t)(t + 2) * NM];
                if (buf) x1b = nv; else x1a = nv;
            }
            if (kq == 0) t2_s[jj] = sg * xmv;   // u * xm
        }
        __syncthreads();

        if (!g) {
            const float hn = fmaf(sg, h_reg, t2_s[jj]);
            h_reg = hn;
            const float hn2 = __shfl_down_sync(0xffffffffu, hn, 4); // row jj+1

            if ((lane & 4) == 0) {   // pair sender (jj even)
                if (kq == 0) {
                    *(float2*)&g_H[base + (size_t)t * NM] = make_float2(hn, hn2);
                    if (t == NS - 1 && hfinal)
                        *(float2*)&hfinal[b * NM + j] = make_float2(hn, hn2);
                }
                if (t + 1 < NS) {
                    unsigned long long pkt =
                        (unsigned long long)__float_as_uint(hn) |
                        ((unsigned long long)__float_as_uint(hn2) << 32);
                    const int nb = buf ^ 1;
                    #pragma unroll
                    for (int d2 = 0; d2 < 2; ++d2) {
                        const uint32_t rdaddr = nb ? rd1[d2] : rd0[d2];
                        const uint32_t rmaddr = nb ? rm1[d2] : rm0[d2];
                        asm volatile(
                            "st.async.shared::cluster.mbarrier::complete_tx::bytes.b64 [%0], %1, [%2];"
                            :: "r"(rdaddr), "l"(pkt), "r"(rmaddr) : "memory");
                    }
                }
            }
        }
    }

    CLUSTER_SYNC_();
}

// =====================================================================
extern "C" void kernel_launch(void* const* d_in, const int* in_sizes, int n_in,
                              void* d_out, int out_size)
{
    const float* x  = (const float*)d_in[0];
    const float* Wi = (const float*)d_in[1];
    const float* bi = (const float*)d_in[2];
    const float* Wf = (const float*)d_in[3];
    const float* bf = (const float*)d_in[4];
    const float* Wu = (const float*)d_in[5];
    const float* bu = (const float*)d_in[6];
    const float* Wo = (const float*)d_in[7];
    const float* bo = (const float*)d_in[8];
    float* out = (float*)d_out;

    // Phase 1: xm / xf / xu projections (tf32 tensor cores)
    gemm_kernel<0><<<dim3(NROWS / 128, 6), 256>>>(x, Wi, bi, Wf, bf, Wu, bu, Wo, bo, out);

    // Phase 2: sequential recurrence (16 batches x 8-CTA clusters)
    float* hfinal = nullptr;
    if ((long long)out_size >= (long long)NROWS * ND + (long long)NB * NM)
        hfinal = out + (size_t)NROWS * ND;
    recur_kernel<<<128, 256>>>(Wf, Wu, hfinal);

    // Phase 3: out = x + bo + [X | H] @ Wo^T
    gemm_kernel<1><<<dim3(NROWS / 128, 8), 256>>>(x, Wi, bi, Wf, bf, Wu, bu, Wo, bo, out);
}